// round 11
// baseline (speedup 1.0000x reference)
#include <cuda_runtime.h>
#include <cstdint>
#include <math.h>

// ---------------- problem constants ----------------
#define M_TOK 100352            // 2048 * 49 tokens
#define DIM   384
#define NH    12
#define HD    32
#define NT    49
#define NWIN  64
#define RANK  16
#define QKV_NPACK 2304          // interleaved (main,gate) rows
#define PROJ_NPACK 768
#define SCALE_Q 0.17677669529663687f
#define NKB   (DIM / 8)         // 48 k-blocks of 8

// Fragment-permuted global layouts:
//  A'[m>>4][k>>3][lane][4] : lane=(m&7)*4+(k&3), inner=(m>>3&1)+2*((k>>2)&1)
//  B'[n>>3][k>>3][lane][2] : lane=(n&7)*4+(k&3), inner=(k>>2)&1
#define A_MB_STRIDE (NKB * 128)   // 6144 floats per 16-row block
#define B_NB_STRIDE (NKB * 64)    // 3072 floats per 8-row block

// Per-(b,h) attention fragment blocks (padding rows stay zero: never written)
#define QF_STRIDE 2048            // [4 mb][4 kb][32 lane][4]
#define KF_STRIDE 1792            // [7 nb][4 kb][32 lane][2]
#define VF_STRIDE 1792            // [7 kb2][4 nb][32 lane][2]

// ---------------- scratch: device globals ----------------
__device__ float g_Wqkv[QKV_NPACK * DIM];   // B'-permuted packed weights
__device__ float g_Wproj[PROJ_NPACK * DIM];
__device__ float g_bias[NH * NT * NT];
__device__ float g_T[M_TOK * RANK];
__device__ float g_X[M_TOK * DIM];          // A'-permuted tf32-rounded x
__device__ float g_Qf[24576L * QF_STRIDE];  // Q in attn A-frag layout (pre-scaled)
__device__ float g_Kf[24576L * KF_STRIDE];  // K in attn B-frag layout
__device__ float g_Vf[24576L * VF_STRIDE];  // V in attn PV B-frag layout
__device__ float g_AO[M_TOK * DIM];         // A'-permuted tf32-rounded attn output

// ---------------- helpers ----------------
__device__ __forceinline__ float f2tf_f(float f) {
    uint32_t u;
    asm("cvt.rna.tf32.f32 %0, %1;" : "=r"(u) : "f"(f));
    return __uint_as_float(u);
}
__device__ __forceinline__ void mma_tf32(float* c, const float4& a, float b0, float b1) {
    asm volatile(
        "mma.sync.aligned.m16n8k8.row.col.f32.tf32.tf32.f32 "
        "{%0,%1,%2,%3},{%4,%5,%6,%7},{%8,%9},{%0,%1,%2,%3};"
        : "+f"(c[0]), "+f"(c[1]), "+f"(c[2]), "+f"(c[3])
        : "r"(__float_as_uint(a.x)), "r"(__float_as_uint(a.y)),
          "r"(__float_as_uint(a.z)), "r"(__float_as_uint(a.w)),
          "r"(__float_as_uint(b0)), "r"(__float_as_uint(b1)));
}
__device__ __forceinline__ void cp16(void* s, const void* g) {
    uint32_t sa = (uint32_t)__cvta_generic_to_shared(s);
    asm volatile("cp.async.cg.shared.global [%0], [%1], 16;" :: "r"(sa), "l"(g));
}
__device__ __forceinline__ void cp_commit() { asm volatile("cp.async.commit_group;"); }
template <int N>
__device__ __forceinline__ void cp_wait() { asm volatile("cp.async.wait_group %0;" :: "n"(N)); }

__device__ __forceinline__ long a_perm_off(long m, int k) {
    return ((m >> 4) * NKB + (k >> 3)) * 128
         + (((int)(m & 7)) * 4 + (k & 3)) * 4
         + ((int)((m >> 3) & 1)) + (((k >> 2) & 1) << 1);
}

// ---------------- prep ----------------
__global__ void prep_kernel(const float* __restrict__ qkv_w, const float* __restrict__ qkv_res,
                            const float* __restrict__ qkv_gate,
                            const float* __restrict__ proj_w, const float* __restrict__ proj_res,
                            const float* __restrict__ proj_gate,
                            const float* __restrict__ bias_table, const int* __restrict__ rel_index) {
    int stride = gridDim.x * blockDim.x;
    int tid = blockIdx.x * blockDim.x + threadIdx.x;
    auto boff = [](int np, int k) {
        return (long)((np >> 3) * NKB + (k >> 3)) * 64 + ((np & 7) * 4 + (k & 3)) * 2 + ((k >> 2) & 1);
    };
    for (int e = tid; e < (QKV_NPACK / 2) * DIM; e += stride) {
        int n = e / DIM, k = e % DIM;
        g_Wqkv[boff(2 * n, k)]     = f2tf_f(qkv_w[e] + qkv_res[e]);
        g_Wqkv[boff(2 * n + 1, k)] = f2tf_f(qkv_gate[e]);
    }
    for (int e = tid; e < (PROJ_NPACK / 2) * DIM; e += stride) {
        int n = e / DIM, k = e % DIM;
        g_Wproj[boff(2 * n, k)]     = f2tf_f(proj_w[e] + proj_res[e]);
        g_Wproj[boff(2 * n + 1, k)] = f2tf_f(proj_gate[e]);
    }
    for (int e = tid; e < NH * NT * NT; e += stride) {
        int h = e / (NT * NT);
        int ij = e % (NT * NT);
        g_bias[e] = bias_table[rel_index[ij] * NH + h];
    }
}

// ---------------- lora down: T = X @ down^T (fp32); optional permuted tf32 copy ----------------
// PERM=0: X is row-linear. PERM=1: X is A'-fragment-permuted.
#define DSTR 385
template <int PERM>
__global__ void __launch_bounds__(256) lora_down_kernel(const float* __restrict__ X,
                                                        const float* __restrict__ down,
                                                        float* __restrict__ T,
                                                        float* __restrict__ Xr) {
    __shared__ float xs[16][DIM];
    __shared__ float ds[RANK * DSTR];
    long m0 = (long)blockIdx.x * 16;
    if (PERM == 0) {
        for (int e = threadIdx.x; e < 16 * DIM; e += 256)
            xs[e / DIM][e % DIM] = X[m0 * DIM + e];
    } else {
        const float* Xb = X + (m0 >> 4) * A_MB_STRIDE;
        for (int e = threadIdx.x; e < 16 * DIM; e += 256) {
            int kb = e >> 7;
            int rem = e & 127;
            int lane = rem >> 2, inner = rem & 3;
            int ml = (lane >> 2) + ((inner & 1) << 3);
            int k = kb * 8 + (lane & 3) + ((inner >> 1) << 2);
            xs[ml][k] = Xb[e];
        }
    }
    for (int e = threadIdx.x; e < RANK * DIM; e += 256)
        ds[(e / DIM) * DSTR + (e % DIM)] = down[e];
    __syncthreads();
    if (Xr) {
        for (int e = threadIdx.x; e < 16 * DIM; e += 256) {
            int ml = e / DIM, k = e % DIM;
            Xr[a_perm_off(m0 + ml, k)] = f2tf_f(xs[ml][k]);
        }
    }
    int ml = threadIdx.x / RANK;
    int r = threadIdx.x % RANK;
    const float* dr = ds + r * DSTR;
    float acc = 0.f;
#pragma unroll 8
    for (int k = 0; k < DIM; k++) acc += xs[ml][k] * dr[k];
    T[(m0 + ml) * RANK + r] = acc;
}

// ---------------- tf32 mma.sync GEMM, fragment-permuted operands, 3-stage pipeline ----------------
// BM=128 x BNP=256, 8 warps as 2m x 4n, warp tile 64m x 64np (acc 128 regs), 1 CTA/SM.
#define BM 128
#define BNP 256                 // packed columns (128 real outputs)
#define BK 32
#define NCH (DIM / BK)          // 12
#define A_ST (BM * BK)          // 4096 floats / stage
#define B_ST (BNP * BK)         // 8192 floats / stage
#define ST_FL (A_ST + B_ST)     // 12288 floats / stage
#define NSTG 3

template <int MODE>  // 0 = qkv scatter to frag layouts, 1 = proj write
__global__ void __launch_bounds__(256, 1) gemm_mma_kernel(
    const float* __restrict__ A, const float* __restrict__ Bp,
    const float* __restrict__ bias, const float* __restrict__ U,
    const float* __restrict__ T, float* __restrict__ outp) {
    extern __shared__ float sm[];

    int tid = threadIdx.x;
    int warp = tid >> 5, lane = tid & 31;
    int g = lane >> 2, t4 = lane & 3;
    int warp_m = warp >> 2;           // 0..1, 64-row stripes
    int warp_n = warp & 3;            // 0..3, 64-packed stripes
    int wm = warp_m * 64;
    int wn = warp_n * 64;
    int mb_w = warp_m * 4;            // 4 A 16-row blocks per warp
    int nb_w = warp_n * 8;            // 8 B 8-row blocks per warp
    int n0p = blockIdx.x * BNP;       // n FASTEST in grid: A reused via L2
    long m0 = (long)blockIdx.y * BM;
    long mb0 = m0 >> 4;
    int nb0 = n0p >> 3;
    int n0r = n0p >> 1;

    float acc[4][8][4];
#pragma unroll
    for (int i = 0; i < 4; i++)
#pragma unroll
        for (int j = 0; j < 8; j++)
#pragma unroll
            for (int c = 0; c < 4; c++) acc[i][j][c] = 0.f;

    auto load_chunk = [&](int c, int s) {
        float* As = sm + s * ST_FL;
        float* Bs = As + A_ST;
        const float* Agc = A + mb0 * A_MB_STRIDE + c * 512;   // 4 kb * 128 floats per mb
        const float* Bgc = Bp + (long)nb0 * B_NB_STRIDE + c * 256;
#pragma unroll
        for (int q = 0; q < 4; q++) {          // A: 1024 16B chunks (8 mb-runs of 2KB)
            int cid = tid + q * 256;
            int mb = cid >> 7, r = cid & 127;
            cp16(&As[mb * 512 + r * 4], Agc + (long)mb * A_MB_STRIDE + r * 4);
        }
#pragma unroll
        for (int q = 0; q < 8; q++) {          // B: 2048 16B chunks (32 nb-runs of 1KB)
            int cid = tid + q * 256;
            int nb = cid >> 6, r = cid & 63;
            cp16(&Bs[nb * 256 + r * 4], Bgc + (long)nb * B_NB_STRIDE + r * 4);
        }
    };

    load_chunk(0, 0); cp_commit();
    load_chunk(1, 1); cp_commit();
    for (int c = 0; c < NCH; c++) {
        if (c < NCH - 1) cp_wait<1>();
        else cp_wait<0>();
        __syncthreads();
        if (c + 2 < NCH) {
            load_chunk(c + 2, (c + 2) % NSTG);
            cp_commit();
        }
        const float* Ab = sm + (c % NSTG) * ST_FL;
        const float* Bb = Ab + A_ST;
#pragma unroll
        for (int ks = 0; ks < 4; ks++) {
            float4 af[4];
            float2 bf[8];
#pragma unroll
            for (int mi = 0; mi < 4; mi++)
                af[mi] = *(const float4*)&Ab[(((mb_w + mi) << 2) + ks) * 128 + lane * 4];
#pragma unroll
            for (int ni = 0; ni < 8; ni++)
                bf[ni] = *(const float2*)&Bb[(((nb_w + ni) << 2) + ks) * 64 + lane * 2];
#pragma unroll
            for (int mi = 0; mi < 4; mi++)
#pragma unroll
                for (int ni = 0; ni < 8; ni++)
                    mma_tf32(acc[mi][ni], af[mi], bf[ni].x, bf[ni].y);
        }
    }

    // -------- epilogue: stage T/U, lora + bias + sigmoid gate, scatter --------
    float* Ts = sm;              // [128][17]
    float* Us = sm + BM * 17;    // [128][17]
    for (int e = tid; e < BM * RANK; e += 256) {
        int i = e >> 4, r = e & 15;
        Ts[i * 17 + r] = T[(m0 + i) * RANK + r];
    }
    for (int e = tid; e < 128 * RANK; e += 256) {
        int i = e >> 4, r = e & 15;
        Us[i * 17 + r] = U[(n0r + i) * RANK + r];
    }
    __syncthreads();

    float lor[8][8];
#pragma unroll
    for (int i = 0; i < 8; i++)
#pragma unroll
        for (int j = 0; j < 8; j++) lor[i][j] = 0.f;
#pragma unroll
    for (int r = 0; r < RANK; r++) {
        float tv[8], uv[8];
#pragma unroll
        for (int mi = 0; mi < 4; mi++)
#pragma unroll
            for (int rr = 0; rr < 2; rr++)
                tv[mi * 2 + rr] = Ts[(wm + mi * 16 + g + rr * 8) * 17 + r];
#pragma unroll
        for (int ni = 0; ni < 8; ni++)
            uv[ni] = Us[((wn >> 1) + ni * 4 + t4) * 17 + r];
#pragma unroll
        for (int i = 0; i < 8; i++)
#pragma unroll
            for (int j = 0; j < 8; j++) lor[i][j] += tv[i] * uv[j];
    }

    float bv[8];
#pragma unroll
    for (int ni = 0; ni < 8; ni++) bv[ni] = __ldg(&bias[n0r + (wn >> 1) + ni * 4 + t4]);

#pragma unroll
    for (int mi = 0; mi < 4; mi++) {
#pragma unroll
        for (int rr = 0; rr < 2; rr++) {
            long m = m0 + wm + mi * 16 + g + rr * 8;
            long bb = m / NT;
            int t = (int)(m % NT);
#pragma unroll
            for (int ni = 0; ni < 8; ni++) {
                int n = n0r + (wn >> 1) + ni * 4 + t4;
                float mainv = acc[mi][ni][rr * 2 + 0];
                float gatev = acc[mi][ni][rr * 2 + 1];
                float gsig = 1.f / (1.f + __expf(-gatev));
                float val = mainv + bv[ni] + gsig * 2.0f * lor[mi * 2 + rr][ni];
                if (MODE == 0) {
                    int s = n / 384;
                    int rem = n - s * 384;
                    int hh = rem >> 5, d = rem & 31;
                    long bh2 = bb * NH + hh;
                    if (s == 0) {
                        long off = bh2 * QF_STRIDE + (((t >> 4) << 2) + (d >> 3)) * 128
                                 + (((t & 7) << 2) + (d & 3)) * 4 + ((t >> 3) & 1) + (((d >> 2) & 1) << 1);
                        g_Qf[off] = f2tf_f(val * SCALE_Q);
                    } else if (s == 1) {
                        long off = bh2 * KF_STRIDE + (((t >> 3) << 2) + (d >> 3)) * 64
                                 + (((t & 7) << 2) + (d & 3)) * 2 + ((d >> 2) & 1);
                        g_Kf[off] = f2tf_f(val);
                    } else {
                        long off = bh2 * VF_STRIDE + (((t >> 3) << 2) + (d >> 3)) * 64
                                 + (((d & 7) << 2) + (t & 3)) * 2 + ((t >> 2) & 1);
                        g_Vf[off] = f2tf_f(val);
                    }
                } else {
                    outp[m * DIM + n] = val;
                }
            }
        }
    }
}

// ---------------- windowed attention, tensor-core, pre-fragmented operands ----------------
#define SPS 58
__global__ void __launch_bounds__(128, 6) attn_kernel(const float* __restrict__ mask,
                                                      float* __restrict__ AO) {
    __shared__ __align__(16) float qs[QF_STRIDE];
    __shared__ __align__(16) float ks[KF_STRIDE];
    __shared__ __align__(16) float vs[VF_STRIDE];
    __shared__ float sp[64 * SPS];
    __shared__ float rinv[64];
    int bh = blockIdx.x;
    int b = bh / NH, h = bh % NH;
    int wdw = b % NWIN;
    int tid = threadIdx.x;
    int warp = tid >> 5, lane = tid & 31, g = lane >> 2, t4 = lane & 3;

    const float* Qf = g_Qf + (long)bh * QF_STRIDE;
    const float* Kf = g_Kf + (long)bh * KF_STRIDE;
    const float* Vf = g_Vf + (long)bh * VF_STRIDE;
    for (int c = tid; c < QF_STRIDE / 4; c += 128) cp16(&qs[c * 4], Qf + (long)c * 4);
    for (int c = tid; c < KF_STRIDE / 4; c += 128) cp16(&ks[c * 4], Kf + (long)c * 4);
    for (int c = tid; c < VF_STRIDE / 4; c += 128) cp16(&vs[c * 4], Vf + (long)c * 4);
    cp_commit();

    const float* bi = g_bias + h * NT * NT;
    const float* mk = mask + (long)wdw * NT * NT;
    for (int e = tid; e < 64 * SPS; e += 128) {
        int i = e / SPS, j = e - i * SPS;
        sp[e] = (i < NT && j < NT) ? bi[i * NT + j] + mk[i * NT + j] : -1e30f;
    }
    cp_wait<0>();
    __syncthreads();

    int base = (warp * 16 + g) * SPS;
    int base2 = base + 8 * SPS;
    float acc[7][4];
#pragma unroll
    for (int nb = 0; nb < 7; nb++) {
        float2 x = *(const float2*)&sp[base + nb * 8 + 2 * t4];
        float2 y = *(const float2*)&sp[base2 + nb * 8 + 2 * t4];
        acc[nb][0] = x.x; acc[nb][1] = x.y; acc[nb][2] = y.x; acc[nb][3] = y.y;
    }
#pragma unroll
    for (int kb = 0; kb < 4; kb++) {
        float4 a = *(const float4*)&qs[(((warp << 2) + kb) * 32 + lane) * 4];
#pragma unroll
        for (int nb = 0; nb < 7; nb++) {
            float2 bv = *(const float2*)&ks[(((nb << 2) + kb) * 32 + lane) * 2];
            mma_tf32(acc[nb], a, bv.x, bv.y);
        }
    }

    float mx1 = -1e30f, mx2 = -1e30f;
#pragma unroll
    for (int nb = 0; nb < 7; nb++) {
        mx1 = fmaxf(mx1, fmaxf(acc[nb][0], acc[nb][1]));
        mx2 = fmaxf(mx2, fmaxf(acc[nb][2], acc[nb][3]));
    }
    mx1 = fmaxf(mx1, __shfl_xor_sync(0xffffffffu, mx1, 1));
    mx1 = fmaxf(mx1, __shfl_xor_sync(0xffffffffu, mx1, 2));
    mx2 = fmaxf(mx2, __shfl_xor_sync(0xffffffffu, mx2, 1));
    mx2 = fmaxf(mx2, __shfl_xor_sync(0xffffffffu, mx2, 2));
    float s1 = 0.f, s2 = 0.f;
#pragma unroll
    for (int nb = 0; nb < 7; nb++) {
        acc[nb][0] = __expf(acc[nb][0] - mx1);
        acc[nb][1] = __expf(acc[nb][1] - mx1);
        acc[nb][2] = __expf(acc[nb][2] - mx2);
        acc[nb][3] = __expf(acc[nb][3] - mx2);
        s1 += acc[nb][0] + acc[nb][1];
        s2 += acc[nb][2] + acc[nb][3];
    }
    s1 += __shfl_xor_sync(0xffffffffu, s1, 1);
    s1 += __shfl_xor_sync(0xffffffffu, s1, 2);
    s2 += __shfl_xor_sync(0xffffffffu, s2, 1);
    s2 += __shfl_xor_sync(0xffffffffu, s2, 2);
    if (t4 == 0) {
        rinv[warp * 16 + g] = 1.f / s1;
        rinv[warp * 16 + 8 + g] = 1.f / s2;
    }
#pragma unroll
    for (int nb = 0; nb < 7; nb++) {
        *(float2*)&sp[base + nb * 8 + 2 * t4]  = make_float2(f2tf_f(acc[nb][0]), f2tf_f(acc[nb][1]));
        *(float2*)&sp[base2 + nb * 8 + 2 * t4] = make_float2(f2tf_f(acc[nb][2]), f2tf_f(acc[nb][3]));
    }
    __syncwarp();

    float acc2[4][4];
#pragma unroll
    for (int i = 0; i < 4; i++)
#pragma unroll
        for (int j = 0; j < 4; j++) acc2[i][j] = 0.f;
#pragma unroll
    for (int kb2 = 0; kb2 < 7; kb2++) {
        float4 a;
        a.x = sp[base + kb2 * 8 + t4];
        a.y = sp[base2 + kb2 * 8 + t4];
        a.z = sp[base + kb2 * 8 + t4 + 4];
        a.w = sp[base2 + kb2 * 8 + t4 + 4];
#pragma unroll
        for (int nb = 0; nb < 4; nb++) {
            float2 bv = *(const float2*)&vs[(((kb2 << 2) + nb) * 32 + lane) * 2];
            mma_tf32(acc2[nb], a, bv.x, bv.y);
        }
    }

    int i1 = warp * 16 + g, i2 = i1 + 8;
    float ri1 = rinv[i1], ri2 = rinv[i2];
    long m1 = (long)b * NT + i1, m2 = (long)b * NT + i2;
#pragma unroll
    for (int nb = 0; nb < 4; nb++) {
        int d0 = nb * 8 + 2 * t4;
        if (i1 < NT) {
            long off = a_perm_off(m1, h * HD + d0);
            AO[off]     = f2tf_f(acc2[nb][0] * ri1);
            AO[off + 4] = f2tf_f(acc2[nb][1] * ri1);
        }
        if (i2 < NT) {
            long off = a_perm_off(m2, h * HD + d0);
            AO[off]     = f2tf_f(acc2[nb][2] * ri2);
            AO[off + 4] = f2tf_f(acc2[nb][3] * ri2);
        }
    }
}

// ---------------- launch ----------------
extern "C" void kernel_launch(void* const* d_in, const int* in_sizes, int n_in,
                              void* d_out, int out_size) {
    const float* x          = (const float*)d_in[0];
    const float* mask       = (const float*)d_in[1];
    const float* qkv_w      = (const float*)d_in[2];
    const float* qkv_b      = (const float*)d_in[3];
    const float* qkv_down   = (const float*)d_in[4];
    const float* qkv_up     = (const float*)d_in[5];
    const float* qkv_gate   = (const float*)d_in[6];
    const float* qkv_res    = (const float*)d_in[7];
    const float* proj_w     = (const float*)d_in[8];
    const float* proj_b     = (const float*)d_in[9];
    const float* proj_down  = (const float*)d_in[10];
    const float* proj_up    = (const float*)d_in[11];
    const float* proj_gate  = (const float*)d_in[12];
    const float* proj_res   = (const float*)d_in[13];
    const float* bias_table = (const float*)d_in[14];
    const int*   rel_index  = (const int*)d_in[15];
    float* out = (float*)d_out;

    float *pT, *pX, *pAO, *pWq, *pWp;
    cudaGetSymbolAddress((void**)&pT, g_T);
    cudaGetSymbolAddress((void**)&pX, g_X);
    cudaGetSymbolAddress((void**)&pAO, g_AO);
    cudaGetSymbolAddress((void**)&pWq, g_Wqkv);
    cudaGetSymbolAddress((void**)&pWp, g_Wproj);

    int smem = NSTG * ST_FL * sizeof(float);   // 147456 bytes
    cudaFuncSetAttribute(gemm_mma_kernel<0>, cudaFuncAttributeMaxDynamicSharedMemorySize, smem);
    cudaFuncSetAttribute(gemm_mma_kernel<1>, cudaFuncAttributeMaxDynamicSharedMemorySize, smem);

    prep_kernel<<<1024, 256>>>(qkv_w, qkv_res, qkv_gate, proj_w, proj_res, proj_gate,
                               bias_table, rel_index);
    lora_down_kernel<0><<<M_TOK / 16, 256>>>(x, qkv_down, pT, pX);
    dim3 gq(QKV_NPACK / BNP, M_TOK / BM);   // (9, 784): n fastest -> A read once
    gemm_mma_kernel<0><<<gq, 256, smem>>>(pX, pWq, qkv_b, qkv_up, pT, nullptr);
    attn_kernel<<<2048 * NH, 128>>>(mask, pAO);
    lora_down_kernel<1><<<M_TOK / 16, 256>>>(pAO, proj_down, pT, nullptr);
    dim3 gp(PROJ_NPACK / BNP, M_TOK / BM);  // (3, 784)
    gemm_mma_kernel<1><<<gp, 256, smem>>>(pAO, pWp, proj_b, proj_up, pT, out);
}

// round 13
// speedup vs baseline: 1.3082x; 1.3082x over previous
#include <cuda_runtime.h>
#include <cstdint>
#include <math.h>

// ---------------- problem constants ----------------
#define M_TOK 100352            // 2048 * 49 tokens
#define DIM   384
#define NH    12
#define HD    32
#define NT    49
#define NWIN  64
#define RANK  16
#define QKV_NPACK 2304          // interleaved (main,gate) rows
#define PROJ_NPACK 768
#define SCALE_Q 0.17677669529663687f
#define NKB   (DIM / 8)         // 48 k-blocks of 8

// Fragment-permuted global layouts:
//  A'[m>>4][k>>3][lane][4] : lane=(m&7)*4+(k&3), inner=(m>>3&1)+2*((k>>2)&1)
//  B'[n>>3][k>>3][lane][2] : lane=(n&7)*4+(k&3), inner=(k>>2)&1
#define A_MB_STRIDE (NKB * 128)   // 6144 floats per 16-row block
#define B_NB_STRIDE (NKB * 64)    // 3072 floats per 8-row block

// Per-(b,h) attention fragment blocks (padding rows stay zero: never written)
#define QF_STRIDE 2048            // [4 mb][4 kb][32 lane][4]
#define KF_STRIDE 1792            // [7 nb][4 kb][32 lane][2]
#define VF_STRIDE 1792            // [7 kb2][4 nb][32 lane][2]

// ---------------- scratch: device globals ----------------
__device__ float g_Wqkv[QKV_NPACK * DIM];   // B'-permuted packed weights
__device__ float g_Wproj[PROJ_NPACK * DIM];
__device__ float g_bias[NH * NT * NT];
__device__ float g_T[M_TOK * RANK];
__device__ float g_X[M_TOK * DIM];          // A'-permuted tf32-rounded x
__device__ float g_Qf[24576L * QF_STRIDE];  // Q in attn A-frag layout (pre-scaled)
__device__ float g_Kf[24576L * KF_STRIDE];  // K in attn B-frag layout
__device__ float g_Vf[24576L * VF_STRIDE];  // V in attn PV B-frag layout
__device__ float g_AO[M_TOK * DIM];         // A'-permuted tf32-rounded attn output

// ---------------- helpers ----------------
__device__ __forceinline__ float f2tf_f(float f) {
    uint32_t u;
    asm("cvt.rna.tf32.f32 %0, %1;" : "=r"(u) : "f"(f));
    return __uint_as_float(u);
}
__device__ __forceinline__ void mma_tf32(float* c, const float4& a, float b0, float b1) {
    asm volatile(
        "mma.sync.aligned.m16n8k8.row.col.f32.tf32.tf32.f32 "
        "{%0,%1,%2,%3},{%4,%5,%6,%7},{%8,%9},{%0,%1,%2,%3};"
        : "+f"(c[0]), "+f"(c[1]), "+f"(c[2]), "+f"(c[3])
        : "r"(__float_as_uint(a.x)), "r"(__float_as_uint(a.y)),
          "r"(__float_as_uint(a.z)), "r"(__float_as_uint(a.w)),
          "r"(__float_as_uint(b0)), "r"(__float_as_uint(b1)));
}
__device__ __forceinline__ void cp16(void* s, const void* g) {
    uint32_t sa = (uint32_t)__cvta_generic_to_shared(s);
    asm volatile("cp.async.cg.shared.global [%0], [%1], 16;" :: "r"(sa), "l"(g));
}
__device__ __forceinline__ void cp_commit() { asm volatile("cp.async.commit_group;"); }
template <int N>
__device__ __forceinline__ void cp_wait() { asm volatile("cp.async.wait_group %0;" :: "n"(N)); }

__device__ __forceinline__ long a_perm_off(long m, int k) {
    return ((m >> 4) * NKB + (k >> 3)) * 128
         + (((int)(m & 7)) * 4 + (k & 3)) * 4
         + ((int)((m >> 3) & 1)) + (((k >> 2) & 1) << 1);
}

// ---------------- prep ----------------
__global__ void prep_kernel(const float* __restrict__ qkv_w, const float* __restrict__ qkv_res,
                            const float* __restrict__ qkv_gate,
                            const float* __restrict__ proj_w, const float* __restrict__ proj_res,
                            const float* __restrict__ proj_gate,
                            const float* __restrict__ bias_table, const int* __restrict__ rel_index) {
    int stride = gridDim.x * blockDim.x;
    int tid = blockIdx.x * blockDim.x + threadIdx.x;
    auto boff = [](int np, int k) {
        return (long)((np >> 3) * NKB + (k >> 3)) * 64 + ((np & 7) * 4 + (k & 3)) * 2 + ((k >> 2) & 1);
    };
    for (int e = tid; e < (QKV_NPACK / 2) * DIM; e += stride) {
        int n = e / DIM, k = e % DIM;
        g_Wqkv[boff(2 * n, k)]     = f2tf_f(qkv_w[e] + qkv_res[e]);
        g_Wqkv[boff(2 * n + 1, k)] = f2tf_f(qkv_gate[e]);
    }
    for (int e = tid; e < (PROJ_NPACK / 2) * DIM; e += stride) {
        int n = e / DIM, k = e % DIM;
        g_Wproj[boff(2 * n, k)]     = f2tf_f(proj_w[e] + proj_res[e]);
        g_Wproj[boff(2 * n + 1, k)] = f2tf_f(proj_gate[e]);
    }
    for (int e = tid; e < NH * NT * NT; e += stride) {
        int h = e / (NT * NT);
        int ij = e % (NT * NT);
        g_bias[e] = bias_table[rel_index[ij] * NH + h];
    }
}

// ---------------- lora down: T = X @ down^T (fp32); optional permuted tf32 copy ----------------
// PERM=0: X is row-linear. PERM=1: X is A'-fragment-permuted.
#define DSTR 385
template <int PERM>
__global__ void __launch_bounds__(256) lora_down_kernel(const float* __restrict__ X,
                                                        const float* __restrict__ down,
                                                        float* __restrict__ T,
                                                        float* __restrict__ Xr) {
    __shared__ float xs[16][DIM];
    __shared__ float ds[RANK * DSTR];
    long m0 = (long)blockIdx.x * 16;
    if (PERM == 0) {
        for (int e = threadIdx.x; e < 16 * DIM; e += 256)
            xs[e / DIM][e % DIM] = X[m0 * DIM + e];
    } else {
        const float* Xb = X + (m0 >> 4) * A_MB_STRIDE;
        for (int e = threadIdx.x; e < 16 * DIM; e += 256) {
            int kb = e >> 7;
            int rem = e & 127;
            int lane = rem >> 2, inner = rem & 3;
            int ml = (lane >> 2) + ((inner & 1) << 3);
            int k = kb * 8 + (lane & 3) + ((inner >> 1) << 2);
            xs[ml][k] = Xb[e];
        }
    }
    for (int e = threadIdx.x; e < RANK * DIM; e += 256)
        ds[(e / DIM) * DSTR + (e % DIM)] = down[e];
    __syncthreads();
    if (Xr) {
        for (int e = threadIdx.x; e < 16 * DIM; e += 256) {
            int ml = e / DIM, k = e % DIM;
            Xr[a_perm_off(m0 + ml, k)] = f2tf_f(xs[ml][k]);
        }
    }
    int ml = threadIdx.x / RANK;
    int r = threadIdx.x % RANK;
    const float* dr = ds + r * DSTR;
    float acc = 0.f;
#pragma unroll 8
    for (int k = 0; k < DIM; k++) acc += xs[ml][k] * dr[k];
    T[(m0 + ml) * RANK + r] = acc;
}

// ---------------- tf32 mma.sync GEMM, fragment-permuted operands, 3-stage pipeline ----------------
// R10 config: BM=128 x BNP=128, 8 warps as 2m x 4n, warp tile 64m x 32np, 2 CTAs/SM.
#define BM 128
#define BNP 128                 // packed columns (64 real outputs)
#define BK 32
#define NCH (DIM / BK)          // 12
#define A_ST (BM * BK)          // 4096 floats / stage
#define B_ST (BNP * BK)         // 4096 floats / stage
#define ST_FL (A_ST + B_ST)     // 8192 floats / stage
#define NSTG 3

template <int MODE>  // 0 = qkv scatter to frag layouts, 1 = proj write
__global__ void __launch_bounds__(256, 2) gemm_mma_kernel(
    const float* __restrict__ A, const float* __restrict__ Bp,
    const float* __restrict__ bias, const float* __restrict__ U,
    const float* __restrict__ T, float* __restrict__ outp) {
    extern __shared__ float sm[];
    __shared__ __align__(16) float Ts[BM * RANK];   // stride 16 (64B rows): cp.async-aligned
    __shared__ __align__(16) float Us[64 * RANK];

    int tid = threadIdx.x;
    int warp = tid >> 5, lane = tid & 31;
    int g = lane >> 2, t4 = lane & 3;
    int warp_m = warp >> 2;           // 0..1, 64-row stripes
    int warp_n = warp & 3;            // 0..3, 32-packed stripes
    int wm = warp_m * 64;
    int wn = warp_n * 32;
    int mb_w = warp_m * 4;            // 4 A 16-row blocks per warp
    int nb_w = warp_n * 4;            // 4 B 8-row blocks per warp
    int n0p = blockIdx.x * BNP;       // n FASTEST in grid: A reused via L2
    long m0 = (long)blockIdx.y * BM;
    long mb0 = m0 >> 4;
    int nb0 = n0p >> 3;
    int n0r = n0p >> 1;

    float acc[4][4][4];
#pragma unroll
    for (int i = 0; i < 4; i++)
#pragma unroll
        for (int j = 0; j < 4; j++)
#pragma unroll
            for (int c = 0; c < 4; c++) acc[i][j][c] = 0.f;

    auto load_chunk = [&](int c, int s) {
        float* As = sm + s * ST_FL;
        float* Bs = As + A_ST;
        const float* Agc = A + mb0 * A_MB_STRIDE + c * 512;   // 4 kb * 128 floats per mb
        const float* Bgc = Bp + (long)nb0 * B_NB_STRIDE + c * 256;
#pragma unroll
        for (int q = 0; q < 4; q++) {          // A: 1024 16B chunks (8 mb-runs of 2KB)
            int cid = tid + q * 256;
            int mb = cid >> 7, r = cid & 127;
            cp16(&As[mb * 512 + r * 4], Agc + (long)mb * A_MB_STRIDE + r * 4);
        }
#pragma unroll
        for (int q = 0; q < 4; q++) {          // B: 1024 16B chunks (16 nb-runs of 1KB)
            int cid = tid + q * 256;
            int nb = cid >> 6, r = cid & 63;
            cp16(&Bs[nb * 256 + r * 4], Bgc + (long)nb * B_NB_STRIDE + r * 4);
        }
    };

    // prefetch Ts/Us bundled with the first chunk's group (ready by first cp_wait + barrier)
    load_chunk(0, 0);
    {
        // T: 128 rows x 16 floats = 512 16B chunks; U: 64 rows = 256 chunks
        for (int c2 = tid; c2 < 512; c2 += 256)
            cp16(&Ts[c2 * 4], T + m0 * RANK + c2 * 4);
        cp16(&Us[tid * 4], U + (long)n0r * RANK + tid * 4);
    }
    cp_commit();
    load_chunk(1, 1); cp_commit();
    for (int c = 0; c < NCH; c++) {
        if (c < NCH - 1) cp_wait<1>();
        else cp_wait<0>();
        __syncthreads();
        if (c + 2 < NCH) {
            load_chunk(c + 2, (c + 2) % NSTG);
            cp_commit();
        }
        const float* Ab = sm + (c % NSTG) * ST_FL;
        const float* Bb = Ab + A_ST;
#pragma unroll
        for (int ks = 0; ks < 4; ks++) {
            float4 af[4];
            float2 bf[4];
#pragma unroll
            for (int mi = 0; mi < 4; mi++)
                af[mi] = *(const float4*)&Ab[(((mb_w + mi) << 2) + ks) * 128 + lane * 4];
#pragma unroll
            for (int ni = 0; ni < 4; ni++)
                bf[ni] = *(const float2*)&Bb[(((nb_w + ni) << 2) + ks) * 64 + lane * 2];
#pragma unroll
            for (int mi = 0; mi < 4; mi++)
#pragma unroll
                for (int ni = 0; ni < 4; ni++)
                    mma_tf32(acc[mi][ni], af[mi], bf[ni].x, bf[ni].y);
        }
    }

    // -------- epilogue: lora + bias + sigmoid gate, scatter (Ts/Us already staged) --------
    float lor[8][4];
#pragma unroll
    for (int i = 0; i < 8; i++)
#pragma unroll
        for (int j = 0; j < 4; j++) lor[i][j] = 0.f;
#pragma unroll
    for (int r = 0; r < RANK; r++) {
        float tv[8], uv[4];
#pragma unroll
        for (int mi = 0; mi < 4; mi++)
#pragma unroll
            for (int rr = 0; rr < 2; rr++)
                tv[mi * 2 + rr] = Ts[(wm + mi * 16 + g + rr * 8) * RANK + r];
#pragma unroll
        for (int ni = 0; ni < 4; ni++)
            uv[ni] = Us[((wn >> 1) + ni * 4 + t4) * RANK + r];
#pragma unroll
        for (int i = 0; i < 8; i++)
#pragma unroll
            for (int j = 0; j < 4; j++) lor[i][j] += tv[i] * uv[j];
    }

    float bv[4];
#pragma unroll
    for (int ni = 0; ni < 4; ni++) bv[ni] = __ldg(&bias[n0r + (wn >> 1) + ni * 4 + t4]);

#pragma unroll
    for (int mi = 0; mi < 4; mi++) {
#pragma unroll
        for (int rr = 0; rr < 2; rr++) {
            long m = m0 + wm + mi * 16 + g + rr * 8;
            long bb = m / NT;
            int t = (int)(m % NT);
#pragma unroll
            for (int ni = 0; ni < 4; ni++) {
                int n = n0r + (wn >> 1) + ni * 4 + t4;
                float mainv = acc[mi][ni][rr * 2 + 0];
                float gatev = acc[mi][ni][rr * 2 + 1];
                float gsig = 1.f / (1.f + __expf(-gatev));
                float val = mainv + bv[ni] + gsig * 2.0f * lor[mi * 2 + rr][ni];
                if (MODE == 0) {
                    int s = n / 384;
                    int rem = n - s * 384;
                    int hh = rem >> 5, d = rem & 31;
                    long bh2 = bb * NH + hh;
                    if (s == 0) {
                        long off = bh2 * QF_STRIDE + (((t >> 4) << 2) + (d >> 3)) * 128
                                 + (((t & 7) << 2) + (d & 3)) * 4 + ((t >> 3) & 1) + (((d >> 2) & 1) << 1);
                        g_Qf[off] = f2tf_f(val * SCALE_Q);
                    } else if (s == 1) {
                        long off = bh2 * KF_STRIDE + (((t >> 3) << 2) + (d >> 3)) * 64
                                 + (((t & 7) << 2) + (d & 3)) * 2 + ((d >> 2) & 1);
                        g_Kf[off] = f2tf_f(val);
                    } else {
                        long off = bh2 * VF_STRIDE + (((t >> 3) << 2) + (d >> 3)) * 64
                                 + (((d & 7) << 2) + (t & 3)) * 2 + ((t >> 2) & 1);
                        g_Vf[off] = f2tf_f(val);
                    }
                } else {
                    outp[m * DIM + n] = val;
                }
            }
        }
    }
}

// ---------------- windowed attention, tensor-core, pre-fragmented operands ----------------
#define SPS 58
__global__ void __launch_bounds__(128, 6) attn_kernel(const float* __restrict__ mask,
                                                      float* __restrict__ AO) {
    __shared__ __align__(16) float qs[QF_STRIDE];
    __shared__ __align__(16) float ks[KF_STRIDE];
    __shared__ __align__(16) float vs[VF_STRIDE];
    __shared__ float sp[64 * SPS];
    __shared__ float rinv[64];
    int bh = blockIdx.x;
    int b = bh / NH, h = bh % NH;
    int wdw = b % NWIN;
    int tid = threadIdx.x;
    int warp = tid >> 5, lane = tid & 31, g = lane >> 2, t4 = lane & 3;

    const float* Qf = g_Qf + (long)bh * QF_STRIDE;
    const float* Kf = g_Kf + (long)bh * KF_STRIDE;
    const float* Vf = g_Vf + (long)bh * VF_STRIDE;
    for (int c = tid; c < QF_STRIDE / 4; c += 128) cp16(&qs[c * 4], Qf + (long)c * 4);
    for (int c = tid; c < KF_STRIDE / 4; c += 128) cp16(&ks[c * 4], Kf + (long)c * 4);
    for (int c = tid; c < VF_STRIDE / 4; c += 128) cp16(&vs[c * 4], Vf + (long)c * 4);
    cp_commit();

    // score board fill with incremental (i, j) tracking: no divides in loop
    const float* bi = g_bias + h * NT * NT;
    const float* mk = mask + (long)wdw * NT * NT;
    {
        int i = tid / SPS, j = tid % SPS;   // one divide up front
        int e = tid;
#pragma unroll 4
        for (int it = 0; it < 64 * SPS / 128; it++) {
            float v = -1e30f;
            if (i < NT && j < NT) {
                int idx = i * NT + j;
                v = bi[idx] + mk[idx];
            }
            sp[e] = v;
            e += 128;
            i += 2; j += 12;
            if (j >= SPS) { j -= SPS; i += 1; }
        }
    }
    cp_wait<0>();
    __syncthreads();

    int base = (warp * 16 + g) * SPS;
    int base2 = base + 8 * SPS;
    float acc[7][4];
#pragma unroll
    for (int nb = 0; nb < 7; nb++) {
        float2 x = *(const float2*)&sp[base + nb * 8 + 2 * t4];
        float2 y = *(const float2*)&sp[base2 + nb * 8 + 2 * t4];
        acc[nb][0] = x.x; acc[nb][1] = x.y; acc[nb][2] = y.x; acc[nb][3] = y.y;
    }
#pragma unroll
    for (int kb = 0; kb < 4; kb++) {
        float4 a = *(const float4*)&qs[(((warp << 2) + kb) * 32 + lane) * 4];
#pragma unroll
        for (int nb = 0; nb < 7; nb++) {
            float2 bv = *(const float2*)&ks[(((nb << 2) + kb) * 32 + lane) * 2];
            mma_tf32(acc[nb], a, bv.x, bv.y);
        }
    }

    float mx1 = -1e30f, mx2 = -1e30f;
#pragma unroll
    for (int nb = 0; nb < 7; nb++) {
        mx1 = fmaxf(mx1, fmaxf(acc[nb][0], acc[nb][1]));
        mx2 = fmaxf(mx2, fmaxf(acc[nb][2], acc[nb][3]));
    }
    mx1 = fmaxf(mx1, __shfl_xor_sync(0xffffffffu, mx1, 1));
    mx1 = fmaxf(mx1, __shfl_xor_sync(0xffffffffu, mx1, 2));
    mx2 = fmaxf(mx2, __shfl_xor_sync(0xffffffffu, mx2, 1));
    mx2 = fmaxf(mx2, __shfl_xor_sync(0xffffffffu, mx2, 2));
    float s1 = 0.f, s2 = 0.f;
#pragma unroll
    for (int nb = 0; nb < 7; nb++) {
        acc[nb][0] = __expf(acc[nb][0] - mx1);
        acc[nb][1] = __expf(acc[nb][1] - mx1);
        acc[nb][2] = __expf(acc[nb][2] - mx2);
        acc[nb][3] = __expf(acc[nb][3] - mx2);
        s1 += acc[nb][0] + acc[nb][1];
        s2 += acc[nb][2] + acc[nb][3];
    }
    s1 += __shfl_xor_sync(0xffffffffu, s1, 1);
    s1 += __shfl_xor_sync(0xffffffffu, s1, 2);
    s2 += __shfl_xor_sync(0xffffffffu, s2, 1);
    s2 += __shfl_xor_sync(0xffffffffu, s2, 2);
    if (t4 == 0) {
        rinv[warp * 16 + g] = 1.f / s1;
        rinv[warp * 16 + 8 + g] = 1.f / s2;
    }
#pragma unroll
    for (int nb = 0; nb < 7; nb++) {
        *(float2*)&sp[base + nb * 8 + 2 * t4]  = make_float2(f2tf_f(acc[nb][0]), f2tf_f(acc[nb][1]));
        *(float2*)&sp[base2 + nb * 8 + 2 * t4] = make_float2(f2tf_f(acc[nb][2]), f2tf_f(acc[nb][3]));
    }
    __syncwarp();

    float acc2[4][4];
#pragma unroll
    for (int i = 0; i < 4; i++)
#pragma unroll
        for (int j = 0; j < 4; j++) acc2[i][j] = 0.f;
#pragma unroll
    for (int kb2 = 0; kb2 < 7; kb2++) {
        float4 a;
        a.x = sp[base + kb2 * 8 + t4];
        a.y = sp[base2 + kb2 * 8 + t4];
        a.z = sp[base + kb2 * 8 + t4 + 4];
        a.w = sp[base2 + kb2 * 8 + t4 + 4];
#pragma unroll
        for (int nb = 0; nb < 4; nb++) {
            float2 bv = *(const float2*)&vs[(((kb2 << 2) + nb) * 32 + lane) * 2];
            mma_tf32(acc2[nb], a, bv.x, bv.y);
        }
    }

    int i1 = warp * 16 + g, i2 = i1 + 8;
    float ri1 = rinv[i1], ri2 = rinv[i2];
    long m1 = (long)b * NT + i1, m2 = (long)b * NT + i2;
#pragma unroll
    for (int nb = 0; nb < 4; nb++) {
        int d0 = nb * 8 + 2 * t4;
        if (i1 < NT) {
            long off = a_perm_off(m1, h * HD + d0);
            AO[off]     = f2tf_f(acc2[nb][0] * ri1);
            AO[off + 4] = f2tf_f(acc2[nb][1] * ri1);
        }
        if (i2 < NT) {
            long off = a_perm_off(m2, h * HD + d0);
            AO[off]     = f2tf_f(acc2[nb][2] * ri2);
            AO[off + 4] = f2tf_f(acc2[nb][3] * ri2);
        }
    }
}

// ---------------- launch ----------------
extern "C" void kernel_launch(void* const* d_in, const int* in_sizes, int n_in,
                              void* d_out, int out_size) {
    const float* x          = (const float*)d_in[0];
    const float* mask       = (const float*)d_in[1];
    const float* qkv_w      = (const float*)d_in[2];
    const float* qkv_b      = (const float*)d_in[3];
    const float* qkv_down   = (const float*)d_in[4];
    const float* qkv_up     = (const float*)d_in[5];
    const float* qkv_gate   = (const float*)d_in[6];
    const float* qkv_res    = (const float*)d_in[7];
    const float* proj_w     = (const float*)d_in[8];
    const float* proj_b     = (const float*)d_in[9];
    const float* proj_down  = (const float*)d_in[10];
    const float* proj_up    = (const float*)d_in[11];
    const float* proj_gate  = (const float*)d_in[12];
    const float* proj_res   = (const float*)d_in[13];
    const float* bias_table = (const float*)d_in[14];
    const int*   rel_index  = (const int*)d_in[15];
    float* out = (float*)d_out;

    float *pT, *pX, *pAO, *pWq, *pWp;
    cudaGetSymbolAddress((void**)&pT, g_T);
    cudaGetSymbolAddress((void**)&pX, g_X);
    cudaGetSymbolAddress((void**)&pAO, g_AO);
    cudaGetSymbolAddress((void**)&pWq, g_Wqkv);
    cudaGetSymbolAddress((void**)&pWp, g_Wproj);

    int smem = NSTG * ST_FL * sizeof(float);   // 98304 bytes dynamic (+12KB static)
    cudaFuncSetAttribute(gemm_mma_kernel<0>, cudaFuncAttributeMaxDynamicSharedMemorySize, smem);
    cudaFuncSetAttribute(gemm_mma_kernel<1>, cudaFuncAttributeMaxDynamicSharedMemorySize, smem);

    prep_kernel<<<1024, 256>>>(qkv_w, qkv_res, qkv_gate, proj_w, proj_res, proj_gate,
                               bias_table, rel_index);
    lora_down_kernel<0><<<M_TOK / 16, 256>>>(x, qkv_down, pT, pX);
    dim3 gq(QKV_NPACK / BNP, M_TOK / BM);   // (18, 784): n fastest -> A read once
    gemm_mma_kernel<0><<<gq, 256, smem>>>(pX, pWq, qkv_b, qkv_up, pT, nullptr);
    attn_kernel<<<2048 * NH, 128>>>(mask, pAO);
    lora_down_kernel<1><<<M_TOK / 16, 256>>>(pAO, proj_down, pT, nullptr);
    dim3 gp(PROJ_NPACK / BNP, M_TOK / BM);  // (6, 784)
    gemm_mma_kernel<1><<<gp, 256, smem>>>(pAO, pWp, proj_b, proj_up, pT, out);
}

// round 14
// speedup vs baseline: 1.3220x; 1.0105x over previous
#include <cuda_runtime.h>
#include <cstdint>
#include <math.h>

// ---------------- problem constants ----------------
#define M_TOK 100352            // 2048 * 49 tokens
#define DIM   384
#define NH    12
#define HD    32
#define NT    49
#define NWIN  64
#define RANK  16
#define QKV_NPACK 2304          // interleaved (main,gate) rows
#define PROJ_NPACK 768
#define SCALE_Q 0.17677669529663687f
#define NKB   (DIM / 8)         // 48 k-blocks of 8

// Fragment-permuted global layouts:
//  A'[m>>4][k>>3][lane][4] : lane=(m&7)*4+(k&3), inner=(m>>3&1)+2*((k>>2)&1)
//  B'[n>>3][k>>3][lane][2] : lane=(n&7)*4+(k&3), inner=(k>>2)&1
#define A_MB_STRIDE (NKB * 128)   // 6144 floats per 16-row block
#define B_NB_STRIDE (NKB * 64)    // 3072 floats per 8-row block

// Per-(b,h) attention fragment blocks (padding rows stay zero: never written)
#define QF_STRIDE 2048            // [4 mb][4 kb][32 lane][4]
#define KF_STRIDE 1792            // [7 nb][4 kb][32 lane][2]
#define VF_STRIDE 1792            // [7 kb2][4 nb][32 lane][2]

// ---------------- scratch: device globals ----------------
__device__ float g_Wqkv[QKV_NPACK * DIM];   // B'-permuted packed weights
__device__ float g_Wproj[PROJ_NPACK * DIM];
__device__ float g_bias[NH * NT * NT];
__device__ float g_T[M_TOK * RANK];
__device__ float g_X[M_TOK * DIM];          // A'-permuted tf32-rounded x
__device__ float g_Qf[24576L * QF_STRIDE];  // Q in attn A-frag layout (pre-scaled)
__device__ float g_Kf[24576L * KF_STRIDE];  // K in attn B-frag layout
__device__ float g_Vf[24576L * VF_STRIDE];  // V in attn PV B-frag layout
__device__ float g_AO[M_TOK * DIM];         // A'-permuted tf32-rounded attn output

// ---------------- helpers ----------------
__device__ __forceinline__ float f2tf_f(float f) {
    uint32_t u;
    asm("cvt.rna.tf32.f32 %0, %1;" : "=r"(u) : "f"(f));
    return __uint_as_float(u);
}
__device__ __forceinline__ void mma_tf32(float* c, const float4& a, float b0, float b1) {
    asm volatile(
        "mma.sync.aligned.m16n8k8.row.col.f32.tf32.tf32.f32 "
        "{%0,%1,%2,%3},{%4,%5,%6,%7},{%8,%9},{%0,%1,%2,%3};"
        : "+f"(c[0]), "+f"(c[1]), "+f"(c[2]), "+f"(c[3])
        : "r"(__float_as_uint(a.x)), "r"(__float_as_uint(a.y)),
          "r"(__float_as_uint(a.z)), "r"(__float_as_uint(a.w)),
          "r"(__float_as_uint(b0)), "r"(__float_as_uint(b1)));
}
__device__ __forceinline__ void cp16(void* s, const void* g) {
    uint32_t sa = (uint32_t)__cvta_generic_to_shared(s);
    asm volatile("cp.async.cg.shared.global [%0], [%1], 16;" :: "r"(sa), "l"(g));
}
__device__ __forceinline__ void cp_commit() { asm volatile("cp.async.commit_group;"); }
template <int N>
__device__ __forceinline__ void cp_wait() { asm volatile("cp.async.wait_group %0;" :: "n"(N)); }

__device__ __forceinline__ long a_perm_off(long m, int k) {
    return ((m >> 4) * NKB + (k >> 3)) * 128
         + (((int)(m & 7)) * 4 + (k & 3)) * 4
         + ((int)((m >> 3) & 1)) + (((k >> 2) & 1) << 1);
}

// ---------------- prep ----------------
__global__ void prep_kernel(const float* __restrict__ qkv_w, const float* __restrict__ qkv_res,
                            const float* __restrict__ qkv_gate,
                            const float* __restrict__ proj_w, const float* __restrict__ proj_res,
                            const float* __restrict__ proj_gate,
                            const float* __restrict__ bias_table, const int* __restrict__ rel_index) {
    int stride = gridDim.x * blockDim.x;
    int tid = blockIdx.x * blockDim.x + threadIdx.x;
    auto boff = [](int np, int k) {
        return (long)((np >> 3) * NKB + (k >> 3)) * 64 + ((np & 7) * 4 + (k & 3)) * 2 + ((k >> 2) & 1);
    };
    for (int e = tid; e < (QKV_NPACK / 2) * DIM; e += stride) {
        int n = e / DIM, k = e % DIM;
        g_Wqkv[boff(2 * n, k)]     = f2tf_f(qkv_w[e] + qkv_res[e]);
        g_Wqkv[boff(2 * n + 1, k)] = f2tf_f(qkv_gate[e]);
    }
    for (int e = tid; e < (PROJ_NPACK / 2) * DIM; e += stride) {
        int n = e / DIM, k = e % DIM;
        g_Wproj[boff(2 * n, k)]     = f2tf_f(proj_w[e] + proj_res[e]);
        g_Wproj[boff(2 * n + 1, k)] = f2tf_f(proj_gate[e]);
    }
    for (int e = tid; e < NH * NT * NT; e += stride) {
        int h = e / (NT * NT);
        int ij = e % (NT * NT);
        g_bias[e] = bias_table[rel_index[ij] * NH + h];
    }
}

// ---------------- lora down: T = X @ down^T (fp32), float4 paths ----------------
// PERM=0: X row-linear (+ writes permuted tf32 copy to Xr). PERM=1: X A'-permuted.
#define DS4 97     // float4 row stride for staged down (388 floats)
template <int PERM>
__global__ void __launch_bounds__(256) lora_down_kernel(const float* __restrict__ X,
                                                        const float* __restrict__ down,
                                                        float* __restrict__ T,
                                                        float* __restrict__ Xr) {
    __shared__ __align__(16) float xs[16 * DIM];
    __shared__ __align__(16) float ds[RANK * DS4 * 4];
    long m0 = (long)blockIdx.x * 16;
    int tid = threadIdx.x;
    if (PERM == 0) {
        const float4* Xb = (const float4*)(X + m0 * DIM);
        float4* xs4 = (float4*)xs;
        for (int e = tid; e < 16 * DIM / 4; e += 256) xs4[e] = Xb[e];
    } else {
        // source is A'-permuted: contiguous float4 -> 4 scattered smem scalars
        const float4* Xb = (const float4*)(X + (m0 >> 4) * A_MB_STRIDE);
        for (int e4 = tid; e4 < 16 * DIM / 4; e4 += 256) {
            int e = e4 * 4;
            int kb = e >> 7;
            int lane = (e & 127) >> 2;
            int ml = lane >> 2;
            int k = kb * 8 + (lane & 3);
            float4 v = Xb[e4];
            xs[ml * DIM + k]             = v.x;   // inner 0: ml, k
            xs[(ml + 8) * DIM + k]       = v.y;   // inner 1: ml+8, k
            xs[ml * DIM + k + 4]         = v.z;   // inner 2: ml, k+4
            xs[(ml + 8) * DIM + k + 4]   = v.w;   // inner 3: ml+8, k+4
        }
    }
    {
        const float4* dg = (const float4*)down;
        for (int e = tid; e < RANK * DIM / 4; e += 256) {
            int r = e / (DIM / 4), k4 = e % (DIM / 4);
            ((float4*)ds)[r * DS4 + k4] = dg[e];
        }
    }
    __syncthreads();
    if (PERM == 0 && Xr) {
        // contiguous permuted-destination writes; scattered smem reads
        float* Xb = Xr + (m0 >> 4) * A_MB_STRIDE;
        for (int e = tid; e < 16 * DIM; e += 256) {
            int kb = e >> 7;
            int rem = e & 127;
            int lane = rem >> 2, inner = rem & 3;
            int ml = (lane >> 2) + ((inner & 1) << 3);
            int k = kb * 8 + (lane & 3) + ((inner >> 1) << 2);
            Xb[e] = f2tf_f(xs[ml * DIM + k]);
        }
    }
    int ml = tid >> 4;
    int r = tid & 15;
    const float4* xv = (const float4*)(xs + ml * DIM);
    const float4* dv = (const float4*)ds + r * DS4;
    float acc = 0.f;
#pragma unroll 8
    for (int k4 = 0; k4 < DIM / 4; k4++) {
        float4 a = xv[k4], b = dv[k4];
        acc += a.x * b.x + a.y * b.y + a.z * b.z + a.w * b.w;
    }
    T[(m0 + ml) * RANK + r] = acc;
}

// ---------------- tf32 mma.sync GEMM, fragment-permuted operands, 3-stage pipeline ----------------
// BM=128 x BNP=128, 8 warps as 2m x 4n, warp tile 64m x 32np, 2 CTAs/SM.
#define BM 128
#define BNP 128                 // packed columns (64 real outputs)
#define BK 32
#define NCH (DIM / BK)          // 12
#define A_ST (BM * BK)          // 4096 floats / stage
#define B_ST (BNP * BK)         // 4096 floats / stage
#define ST_FL (A_ST + B_ST)     // 8192 floats / stage
#define NSTG 3

template <int MODE>  // 0 = qkv scatter to frag layouts, 1 = proj write
__global__ void __launch_bounds__(256, 2) gemm_mma_kernel(
    const float* __restrict__ A, const float* __restrict__ Bp,
    const float* __restrict__ bias, const float* __restrict__ U,
    const float* __restrict__ T, float* __restrict__ outp) {
    extern __shared__ float sm[];
    __shared__ __align__(16) float Ts[BM * RANK];   // stride 16 (64B rows): cp.async-aligned
    __shared__ __align__(16) float Us[64 * RANK];

    int tid = threadIdx.x;
    int warp = tid >> 5, lane = tid & 31;
    int g = lane >> 2, t4 = lane & 3;
    int warp_m = warp >> 2;           // 0..1, 64-row stripes
    int warp_n = warp & 3;            // 0..3, 32-packed stripes
    int wm = warp_m * 64;
    int wn = warp_n * 32;
    int mb_w = warp_m * 4;            // 4 A 16-row blocks per warp
    int nb_w = warp_n * 4;            // 4 B 8-row blocks per warp
    int n0p = blockIdx.x * BNP;       // n FASTEST in grid: A reused via L2
    long m0 = (long)blockIdx.y * BM;
    long mb0 = m0 >> 4;
    int nb0 = n0p >> 3;
    int n0r = n0p >> 1;

    float acc[4][4][4];
#pragma unroll
    for (int i = 0; i < 4; i++)
#pragma unroll
        for (int j = 0; j < 4; j++)
#pragma unroll
            for (int c = 0; c < 4; c++) acc[i][j][c] = 0.f;

    auto load_chunk = [&](int c, int s) {
        float* As = sm + s * ST_FL;
        float* Bs = As + A_ST;
        const float* Agc = A + mb0 * A_MB_STRIDE + c * 512;   // 4 kb * 128 floats per mb
        const float* Bgc = Bp + (long)nb0 * B_NB_STRIDE + c * 256;
#pragma unroll
        for (int q = 0; q < 4; q++) {          // A: 1024 16B chunks (8 mb-runs of 2KB)
            int cid = tid + q * 256;
            int mb = cid >> 7, r = cid & 127;
            cp16(&As[mb * 512 + r * 4], Agc + (long)mb * A_MB_STRIDE + r * 4);
        }
#pragma unroll
        for (int q = 0; q < 4; q++) {          // B: 1024 16B chunks (16 nb-runs of 1KB)
            int cid = tid + q * 256;
            int nb = cid >> 6, r = cid & 63;
            cp16(&Bs[nb * 256 + r * 4], Bgc + (long)nb * B_NB_STRIDE + r * 4);
        }
    };

    // prefetch Ts/Us bundled with the first chunk's group (ready by first cp_wait + barrier)
    load_chunk(0, 0);
    {
        for (int c2 = tid; c2 < 512; c2 += 256)
            cp16(&Ts[c2 * 4], T + m0 * RANK + c2 * 4);
        cp16(&Us[tid * 4], U + (long)n0r * RANK + tid * 4);
    }
    cp_commit();
    load_chunk(1, 1); cp_commit();
    for (int c = 0; c < NCH; c++) {
        if (c < NCH - 1) cp_wait<1>();
        else cp_wait<0>();
        __syncthreads();
        if (c + 2 < NCH) {
            load_chunk(c + 2, (c + 2) % NSTG);
            cp_commit();
        }
        const float* Ab = sm + (c % NSTG) * ST_FL;
        const float* Bb = Ab + A_ST;
#pragma unroll
        for (int ks = 0; ks < 4; ks++) {
            float4 af[4];
            float2 bf[4];
#pragma unroll
            for (int mi = 0; mi < 4; mi++)
                af[mi] = *(const float4*)&Ab[(((mb_w + mi) << 2) + ks) * 128 + lane * 4];
#pragma unroll
            for (int ni = 0; ni < 4; ni++)
                bf[ni] = *(const float2*)&Bb[(((nb_w + ni) << 2) + ks) * 64 + lane * 2];
#pragma unroll
            for (int mi = 0; mi < 4; mi++)
#pragma unroll
                for (int ni = 0; ni < 4; ni++)
                    mma_tf32(acc[mi][ni], af[mi], bf[ni].x, bf[ni].y);
        }
    }

    // -------- epilogue: lora + bias + sigmoid gate, scatter (Ts/Us already staged) --------
    float lor[8][4];
#pragma unroll
    for (int i = 0; i < 8; i++)
#pragma unroll
        for (int j = 0; j < 4; j++) lor[i][j] = 0.f;
#pragma unroll
    for (int r = 0; r < RANK; r++) {
        float tv[8], uv[4];
#pragma unroll
        for (int mi = 0; mi < 4; mi++)
#pragma unroll
            for (int rr = 0; rr < 2; rr++)
                tv[mi * 2 + rr] = Ts[(wm + mi * 16 + g + rr * 8) * RANK + r];
#pragma unroll
        for (int ni = 0; ni < 4; ni++)
            uv[ni] = Us[((wn >> 1) + ni * 4 + t4) * RANK + r];
#pragma unroll
        for (int i = 0; i < 8; i++)
#pragma unroll
            for (int j = 0; j < 4; j++) lor[i][j] += tv[i] * uv[j];
    }

    float bv[4];
#pragma unroll
    for (int ni = 0; ni < 4; ni++) bv[ni] = __ldg(&bias[n0r + (wn >> 1) + ni * 4 + t4]);

#pragma unroll
    for (int mi = 0; mi < 4; mi++) {
#pragma unroll
        for (int rr = 0; rr < 2; rr++) {
            long m = m0 + wm + mi * 16 + g + rr * 8;
            long bb = m / NT;
            int t = (int)(m % NT);
#pragma unroll
            for (int ni = 0; ni < 4; ni++) {
                int n = n0r + (wn >> 1) + ni * 4 + t4;
                float mainv = acc[mi][ni][rr * 2 + 0];
                float gatev = acc[mi][ni][rr * 2 + 1];
                float gsig = 1.f / (1.f + __expf(-gatev));
                float val = mainv + bv[ni] + gsig * 2.0f * lor[mi * 2 + rr][ni];
                if (MODE == 0) {
                    int s = n / 384;
                    int rem = n - s * 384;
                    int hh = rem >> 5, d = rem & 31;
                    long bh2 = bb * NH + hh;
                    if (s == 0) {
                        long off = bh2 * QF_STRIDE + (((t >> 4) << 2) + (d >> 3)) * 128
                                 + (((t & 7) << 2) + (d & 3)) * 4 + ((t >> 3) & 1) + (((d >> 2) & 1) << 1);
                        g_Qf[off] = f2tf_f(val * SCALE_Q);
                    } else if (s == 1) {
                        long off = bh2 * KF_STRIDE + (((t >> 3) << 2) + (d >> 3)) * 64
                                 + (((t & 7) << 2) + (d & 3)) * 2 + ((d >> 2) & 1);
                        g_Kf[off] = f2tf_f(val);
                    } else {
                        long off = bh2 * VF_STRIDE + (((t >> 3) << 2) + (d >> 3)) * 64
                                 + (((d & 7) << 2) + (t & 3)) * 2 + ((t >> 2) & 1);
                        g_Vf[off] = f2tf_f(val);
                    }
                } else {
                    outp[m * DIM + n] = val;
                }
            }
        }
    }
}

// ---------------- windowed attention, tensor-core, pre-fragmented operands ----------------
#define SPS 58
__global__ void __launch_bounds__(128, 6) attn_kernel(const float* __restrict__ mask,
                                                      float* __restrict__ AO) {
    __shared__ __align__(16) float qs[QF_STRIDE];
    __shared__ __align__(16) float ks[KF_STRIDE];
    __shared__ __align__(16) float vs[VF_STRIDE];
    __shared__ float sp[64 * SPS];
    __shared__ float rinv[64];
    int bh = blockIdx.x;
    int b = bh / NH, h = bh % NH;
    int wdw = b % NWIN;
    int tid = threadIdx.x;
    int warp = tid >> 5, lane = tid & 31, g = lane >> 2, t4 = lane & 3;

    const float* Qf = g_Qf + (long)bh * QF_STRIDE;
    const float* Kf = g_Kf + (long)bh * KF_STRIDE;
    const float* Vf = g_Vf + (long)bh * VF_STRIDE;
    for (int c = tid; c < QF_STRIDE / 4; c += 128) cp16(&qs[c * 4], Qf + (long)c * 4);
    for (int c = tid; c < KF_STRIDE / 4; c += 128) cp16(&ks[c * 4], Kf + (long)c * 4);
    for (int c = tid; c < VF_STRIDE / 4; c += 128) cp16(&vs[c * 4], Vf + (long)c * 4);
    cp_commit();

    // score board fill with incremental (i, j) tracking: no divides in loop
    const float* bi = g_bias + h * NT * NT;
    const float* mk = mask + (long)wdw * NT * NT;
    {
        int i = tid / SPS, j = tid % SPS;   // one divide up front
        int e = tid;
#pragma unroll 4
        for (int it = 0; it < 64 * SPS / 128; it++) {
            float v = -1e30f;
            if (i < NT && j < NT) {
                int idx = i * NT + j;
                v = bi[idx] + mk[idx];
            }
            sp[e] = v;
            e += 128;
            i += 2; j += 12;
            if (j >= SPS) { j -= SPS; i += 1; }
        }
    }
    cp_wait<0>();
    __syncthreads();

    int base = (warp * 16 + g) * SPS;
    int base2 = base + 8 * SPS;
    float acc[7][4];
#pragma unroll
    for (int nb = 0; nb < 7; nb++) {
        float2 x = *(const float2*)&sp[base + nb * 8 + 2 * t4];
        float2 y = *(const float2*)&sp[base2 + nb * 8 + 2 * t4];
        acc[nb][0] = x.x; acc[nb][1] = x.y; acc[nb][2] = y.x; acc[nb][3] = y.y;
    }
#pragma unroll
    for (int kb = 0; kb < 4; kb++) {
        float4 a = *(const float4*)&qs[(((warp << 2) + kb) * 32 + lane) * 4];
#pragma unroll
        for (int nb = 0; nb < 7; nb++) {
            float2 bv = *(const float2*)&ks[(((nb << 2) + kb) * 32 + lane) * 2];
            mma_tf32(acc[nb], a, bv.x, bv.y);
        }
    }

    float mx1 = -1e30f, mx2 = -1e30f;
#pragma unroll
    for (int nb = 0; nb < 7; nb++) {
        mx1 = fmaxf(mx1, fmaxf(acc[nb][0], acc[nb][1]));
        mx2 = fmaxf(mx2, fmaxf(acc[nb][2], acc[nb][3]));
    }
    mx1 = fmaxf(mx1, __shfl_xor_sync(0xffffffffu, mx1, 1));
    mx1 = fmaxf(mx1, __shfl_xor_sync(0xffffffffu, mx1, 2));
    mx2 = fmaxf(mx2, __shfl_xor_sync(0xffffffffu, mx2, 1));
    mx2 = fmaxf(mx2, __shfl_xor_sync(0xffffffffu, mx2, 2));
    float s1 = 0.f, s2 = 0.f;
#pragma unroll
    for (int nb = 0; nb < 7; nb++) {
        acc[nb][0] = __expf(acc[nb][0] - mx1);
        acc[nb][1] = __expf(acc[nb][1] - mx1);
        acc[nb][2] = __expf(acc[nb][2] - mx2);
        acc[nb][3] = __expf(acc[nb][3] - mx2);
        s1 += acc[nb][0] + acc[nb][1];
        s2 += acc[nb][2] + acc[nb][3];
    }
    s1 += __shfl_xor_sync(0xffffffffu, s1, 1);
    s1 += __shfl_xor_sync(0xffffffffu, s1, 2);
    s2 += __shfl_xor_sync(0xffffffffu, s2, 1);
    s2 += __shfl_xor_sync(0xffffffffu, s2, 2);
    if (t4 == 0) {
        rinv[warp * 16 + g] = 1.f / s1;
        rinv[warp * 16 + 8 + g] = 1.f / s2;
    }
#pragma unroll
    for (int nb = 0; nb < 7; nb++) {
        *(float2*)&sp[base + nb * 8 + 2 * t4]  = make_float2(f2tf_f(acc[nb][0]), f2tf_f(acc[nb][1]));
        *(float2*)&sp[base2 + nb * 8 + 2 * t4] = make_float2(f2tf_f(acc[nb][2]), f2tf_f(acc[nb][3]));
    }
    __syncwarp();

    float acc2[4][4];
#pragma unroll
    for (int i = 0; i < 4; i++)
#pragma unroll
        for (int j = 0; j < 4; j++) acc2[i][j] = 0.f;
#pragma unroll
    for (int kb2 = 0; kb2 < 7; kb2++) {
        float4 a;
        a.x = sp[base + kb2 * 8 + t4];
        a.y = sp[base2 + kb2 * 8 + t4];
        a.z = sp[base + kb2 * 8 + t4 + 4];
        a.w = sp[base2 + kb2 * 8 + t4 + 4];
#pragma unroll
        for (int nb = 0; nb < 4; nb++) {
            float2 bv = *(const float2*)&vs[(((kb2 << 2) + nb) * 32 + lane) * 2];
            mma_tf32(acc2[nb], a, bv.x, bv.y);
        }
    }

    int i1 = warp * 16 + g, i2 = i1 + 8;
    float ri1 = rinv[i1], ri2 = rinv[i2];
    long m1 = (long)b * NT + i1, m2 = (long)b * NT + i2;
#pragma unroll
    for (int nb = 0; nb < 4; nb++) {
        int d0 = nb * 8 + 2 * t4;
        if (i1 < NT) {
            long off = a_perm_off(m1, h * HD + d0);
            AO[off]     = f2tf_f(acc2[nb][0] * ri1);
            AO[off + 4] = f2tf_f(acc2[nb][1] * ri1);
        }
        if (i2 < NT) {
            long off = a_perm_off(m2, h * HD + d0);
            AO[off]     = f2tf_f(acc2[nb][2] * ri2);
            AO[off + 4] = f2tf_f(acc2[nb][3] * ri2);
        }
    }
}

// ---------------- launch ----------------
extern "C" void kernel_launch(void* const* d_in, const int* in_sizes, int n_in,
                              void* d_out, int out_size) {
    const float* x          = (const float*)d_in[0];
    const float* mask       = (const float*)d_in[1];
    const float* qkv_w      = (const float*)d_in[2];
    const float* qkv_b      = (const float*)d_in[3];
    const float* qkv_down   = (const float*)d_in[4];
    const float* qkv_up     = (const float*)d_in[5];
    const float* qkv_gate   = (const float*)d_in[6];
    const float* qkv_res    = (const float*)d_in[7];
    const float* proj_w     = (const float*)d_in[8];
    const float* proj_b     = (const float*)d_in[9];
    const float* proj_down  = (const float*)d_in[10];
    const float* proj_up    = (const float*)d_in[11];
    const float* proj_gate  = (const float*)d_in[12];
    const float* proj_res   = (const float*)d_in[13];
    const float* bias_table = (const float*)d_in[14];
    const int*   rel_index  = (const int*)d_in[15];
    float* out = (float*)d_out;

    float *pT, *pX, *pAO, *pWq, *pWp;
    cudaGetSymbolAddress((void**)&pT, g_T);
    cudaGetSymbolAddress((void**)&pX, g_X);
    cudaGetSymbolAddress((void**)&pAO, g_AO);
    cudaGetSymbolAddress((void**)&pWq, g_Wqkv);
    cudaGetSymbolAddress((void**)&pWp, g_Wproj);

    int smem = NSTG * ST_FL * sizeof(float);   // 98304 bytes dynamic (+12KB static)
    cudaFuncSetAttribute(gemm_mma_kernel<0>, cudaFuncAttributeMaxDynamicSharedMemorySize, smem);
    cudaFuncSetAttribute(gemm_mma_kernel<1>, cudaFuncAttributeMaxDynamicSharedMemorySize, smem);

    prep_kernel<<<1024, 256>>>(qkv_w, qkv_res, qkv_gate, proj_w, proj_res, proj_gate,
                               bias_table, rel_index);
    lora_down_kernel<0><<<M_TOK / 16, 256>>>(x, qkv_down, pT, pX);
    dim3 gq(QKV_NPACK / BNP, M_TOK / BM);   // (18, 784): n fastest -> A read once
    gemm_mma_kernel<0><<<gq, 256, smem>>>(pX, pWq, qkv_b, qkv_up, pT, nullptr);
    attn_kernel<<<2048 * NH, 128>>>(mask, pAO);
    lora_down_kernel<1><<<M_TOK / 16, 256>>>(pAO, proj_down, pT, nullptr);
    dim3 gp(PROJ_NPACK / BNP, M_TOK / BM);  // (6, 784)
    gemm_mma_kernel<1><<<gp, 256, smem>>>(pAO, pWp, proj_b, proj_up, pT, out);
}